// round 7
// baseline (speedup 1.0000x reference)
#include <cuda_runtime.h>
#include <cstdint>

#define C_IN   8
#define C_OUT  8
#define FSZ    4
#define LLEN   65536
#define LSHIFT 16
#define BATCH  64
#define TILE   4               // output positions per thread
#define TPR    (LLEN / TILE)   // tiles per row = 16384 = 2^14

// ---- packed fp32x2 helpers (Blackwell native f32x2 pipe, PTX-only) ----
__device__ __forceinline__ void fma2(unsigned long long& d,
                                     unsigned long long a,
                                     unsigned long long b) {
    asm("fma.rn.f32x2 %0, %1, %2, %0;" : "+l"(d) : "l"(a), "l"(b));
}
__device__ __forceinline__ unsigned long long pack2(float lo, float hi) {
    unsigned long long r;
    asm("mov.b64 %0, {%1, %2};" : "=l"(r) : "f"(lo), "f"(hi));
    return r;
}

// Each thread computes 4 consecutive L positions for ALL 8 output channels of
// one batch row. Inputs are loaded as ulonglong2 so the even-start f32x2
// operand pairs are the raw halves of the LDG.128 (already even-register-
// aligned -> ZERO packing MOVs); only the 3 odd-start pairs per ci are packed.
// Small accumulator file (16 pairs = 32 regs) keeps total pressure ~80 regs so
// ptxas can keep pairs aligned and we fit 3 CTAs/SM (24 warps).
__global__ __launch_bounds__(256, 3)
void convPbc_1d_kernel(const float* __restrict__ x,
                       const float* __restrict__ W,
                       const float* __restrict__ bias,
                       float* __restrict__ out) {
    __shared__ __align__(16) unsigned long long ws[C_OUT][C_IN][FSZ];
    __shared__ unsigned long long bsp[C_OUT];

    int tid = threadIdx.x;
    if (tid < C_OUT * C_IN * FSZ) {
        float w = W[tid];
        int co = tid >> 5;
        int ci = (tid >> 2) & 7;
        int f  = tid & 3;
        ws[co][ci][f] = pack2(w, w);
    }
    if (tid < C_OUT) {
        float b = bias[tid];
        bsp[tid] = pack2(b, b);
    }
    __syncthreads();

    unsigned int gtid = blockIdx.x * blockDim.x + threadIdx.x;
    int b = gtid >> 14;                 // batch row
    int l = (gtid & (TPR - 1u)) << 2;   // tile start position

    const float* xbase = x + ((b << 3) << LSHIFT) + l;   // ci stride = LLEN
    // wrap tile (l == L-4): second vector comes from row start (circular)
    const int off1 = (l == (LLEN - TILE)) ? -l : 4;      // branch-free select

    // Double-buffered per-ci inputs: v0 = (x0,x1 | x2,x3), v1 = (x4,x5 | x6,x7)
    ulonglong2 v0[2], v1[2];
    {   // prologue: load ci = 0
        v0[0] = *reinterpret_cast<const ulonglong2*>(xbase);
        v1[0] = *reinterpret_cast<const ulonglong2*>(xbase + off1);
    }

    // acc[co][0] -> positions (l, l+1), acc[co][1] -> (l+2, l+3)
    unsigned long long acc[C_OUT][2];
#pragma unroll
    for (int co = 0; co < C_OUT; co++) {
        unsigned long long bb = bsp[co];
        acc[co][0] = bb; acc[co][1] = bb;
    }

#pragma unroll
    for (int ci = 0; ci < C_IN; ci++) {
        int cur = ci & 1;
        int nxt = cur ^ 1;

        // prefetch ci+1 before computing ci
        if (ci + 1 < C_IN) {
            const float* xr = xbase + ((ci + 1) << LSHIFT);
            v0[nxt] = *reinterpret_cast<const ulonglong2*>(xr);
            v1[nxt] = *reinterpret_cast<const ulonglong2*>(xr + off1);
        }

        // even pairs are free: e01 = v0.x, e23 = v0.y, e45 = v1.x
        const float2 f0 = *reinterpret_cast<const float2*>(&v0[cur].x); // x0,x1
        const float2 f1 = *reinterpret_cast<const float2*>(&v0[cur].y); // x2,x3
        const float2 f2 = *reinterpret_cast<const float2*>(&v1[cur].x); // x4,x5
        const float2 f3 = *reinterpret_cast<const float2*>(&v1[cur].y); // x6,x7
        unsigned long long o12 = pack2(f0.y, f1.x);   // (x1,x2)
        unsigned long long o34 = pack2(f1.y, f2.x);   // (x3,x4)
        unsigned long long o56 = pack2(f2.y, f3.x);   // (x5,x6)
        unsigned long long e01 = v0[cur].x;
        unsigned long long e23 = v0[cur].y;
        unsigned long long e45 = v1[cur].x;

        const unsigned long long* wrow = &ws[0][ci][0];  // stride C_IN*FSZ per co
#pragma unroll
        for (int co = 0; co < C_OUT; co++) {
            ulonglong2 wf01 = *reinterpret_cast<const ulonglong2*>(wrow + co * (C_IN * FSZ));
            ulonglong2 wf23 = *reinterpret_cast<const ulonglong2*>(wrow + co * (C_IN * FSZ) + 2);

            fma2(acc[co][0], e01, wf01.x);  // tap 0
            fma2(acc[co][1], e23, wf01.x);
            fma2(acc[co][0], o12, wf01.y);  // tap 1
            fma2(acc[co][1], o34, wf01.y);
            fma2(acc[co][0], e23, wf23.x);  // tap 2
            fma2(acc[co][1], e45, wf23.x);
            fma2(acc[co][0], o34, wf23.y);  // tap 3
            fma2(acc[co][1], o56, wf23.y);
        }
    }

#pragma unroll
    for (int co = 0; co < C_OUT; co++) {
        // store the two aligned 64-bit halves as one 128-bit store
        ulonglong2 st;
        st.x = acc[co][0];
        st.y = acc[co][1];
        *reinterpret_cast<ulonglong2*>(out + (((b << 3) + co) << LSHIFT) + l) = st;
    }
}

extern "C" void kernel_launch(void* const* d_in, const int* in_sizes, int n_in,
                              void* d_out, int out_size) {
    const float* x    = (const float*)d_in[0];
    const float* W    = (const float*)d_in[1];
    const float* bias = (const float*)d_in[2];
    float* out        = (float*)d_out;

    const int threads = 256;
    const int blocks  = (BATCH * TPR) / threads;  // 1,048,576 / 256 = 4096
    convPbc_1d_kernel<<<blocks, threads>>>(x, W, bias, out);
}

// round 14
// speedup vs baseline: 1.3069x; 1.3069x over previous
#include <cuda_runtime.h>
#include <cstdint>

#define C_IN    8
#define C_OUT   8
#define FSZ     4
#define LLEN    65536
#define LSHIFT  16
#define BATCH   64
#define TILE    8                 // output positions per thread
#define TPR     (LLEN / TILE)     // tiles per row = 8192 = 2^13
#define CO_PT   4                 // output channels per thread (co-split by 2)

// ---- packed fp32x2 helpers (Blackwell FFMA2, PTX-only) ----
__device__ __forceinline__ void fma2(unsigned long long& d,
                                     unsigned long long a,
                                     unsigned long long b) {
    asm("fma.rn.f32x2 %0, %1, %2, %0;" : "+l"(d) : "l"(a), "l"(b));
}
__device__ __forceinline__ unsigned long long pack2(float lo, float hi) {
    unsigned long long r;
    asm("mov.b64 %0, {%1, %2};" : "=l"(r) : "f"(lo), "f"(hi));
    return r;
}

// Each thread computes 8 consecutive L positions for 4 of the 8 output
// channels (co-split across thread halves). Even-start f32x2 pairs come
// free out of LDG.128 quads; only 5 odd-start pairs per ci are packed.
// Per (ci,co): 2 broadcast LDS.128 feed 16 FMA2 (1:8 ratio). Accumulators:
// 16 pairs = 32 regs, total ~75 regs -> 3 CTAs/SM.
__global__ __launch_bounds__(256, 3)
void convPbc_1d_kernel(const float* __restrict__ x,
                       const float* __restrict__ W,
                       const float* __restrict__ bias,
                       float* __restrict__ out) {
    __shared__ __align__(16) unsigned long long ws[C_OUT][C_IN][FSZ];
    __shared__ unsigned long long bsp[C_OUT];

    int tid = threadIdx.x;
    if (tid < C_OUT * C_IN * FSZ) {
        float w = W[tid];
        int co = tid >> 5;
        int ci = (tid >> 2) & 7;
        int f  = tid & 3;
        ws[co][ci][f] = pack2(w, w);
    }
    if (tid < C_OUT) {
        float b = bias[tid];
        bsp[tid] = pack2(b, b);
    }
    __syncthreads();

    const int cohalf = tid >> 7;                       // 0 or 1
    const int cobase = cohalf << 2;                    // 0 or 4
    unsigned int tileid = (blockIdx.x << 7) + (tid & 127u);
    int b = tileid >> 13;                              // batch row
    int l = (tileid & (TPR - 1u)) << 3;                // tile start position

    const float* xbase = x + ((b << 3) << LSHIFT) + l; // ci stride = LLEN
    // wrap tile (l == L-8): third quad comes from row start (circular)
    const int off2 = (l == (LLEN - TILE)) ? -l : 8;    // branch-free select

    // acc[c][j] covers positions (l+2j, l+2j+1) for channel cobase+c
    unsigned long long acc[CO_PT][4];
#pragma unroll
    for (int c = 0; c < CO_PT; c++) {
        unsigned long long bb = bsp[cobase + c];
        acc[c][0] = bb; acc[c][1] = bb; acc[c][2] = bb; acc[c][3] = bb;
    }

#pragma unroll
    for (int ci = 0; ci < C_IN; ci++) {
        const float* xr = xbase + (ci << LSHIFT);
        ulonglong2 q0 = *reinterpret_cast<const ulonglong2*>(xr);        // x0..x3
        ulonglong2 q1 = *reinterpret_cast<const ulonglong2*>(xr + 4);    // x4..x7
        ulonglong2 q2 = *reinterpret_cast<const ulonglong2*>(xr + off2); // x8..x11

        // free even-start pairs (aligned halves of LDG.128 quads)
        unsigned long long e0 = q0.x;   // (x0,x1)
        unsigned long long e2 = q0.y;   // (x2,x3)
        unsigned long long e4 = q1.x;   // (x4,x5)
        unsigned long long e6 = q1.y;   // (x6,x7)
        unsigned long long e8 = q2.x;   // (x8,x9)

        // odd-start pairs: 5 packs
        const float2 g0 = *reinterpret_cast<const float2*>(&q0.x);
        const float2 g1 = *reinterpret_cast<const float2*>(&q0.y);
        const float2 g2 = *reinterpret_cast<const float2*>(&q1.x);
        const float2 g3 = *reinterpret_cast<const float2*>(&q1.y);
        const float2 g4 = *reinterpret_cast<const float2*>(&q2.x);
        const float2 g5 = *reinterpret_cast<const float2*>(&q2.y);
        unsigned long long o1 = pack2(g0.y, g1.x);   // (x1,x2)
        unsigned long long o3 = pack2(g1.y, g2.x);   // (x3,x4)
        unsigned long long o5 = pack2(g2.y, g3.x);   // (x5,x6)
        unsigned long long o7 = pack2(g3.y, g4.x);   // (x7,x8)
        unsigned long long o9 = pack2(g4.y, g5.x);   // (x9,x10)

#pragma unroll
        for (int c = 0; c < CO_PT; c++) {
            ulonglong2 wf01 = *reinterpret_cast<const ulonglong2*>(&ws[cobase + c][ci][0]);
            ulonglong2 wf23 = *reinterpret_cast<const ulonglong2*>(&ws[cobase + c][ci][2]);

            // tap 0
            fma2(acc[c][0], e0, wf01.x);
            fma2(acc[c][1], e2, wf01.x);
            fma2(acc[c][2], e4, wf01.x);
            fma2(acc[c][3], e6, wf01.x);
            // tap 1
            fma2(acc[c][0], o1, wf01.y);
            fma2(acc[c][1], o3, wf01.y);
            fma2(acc[c][2], o5, wf01.y);
            fma2(acc[c][3], o7, wf01.y);
            // tap 2
            fma2(acc[c][0], e2, wf23.x);
            fma2(acc[c][1], e4, wf23.x);
            fma2(acc[c][2], e6, wf23.x);
            fma2(acc[c][3], e8, wf23.x);
            // tap 3
            fma2(acc[c][0], o3, wf23.y);
            fma2(acc[c][1], o5, wf23.y);
            fma2(acc[c][2], o7, wf23.y);
            fma2(acc[c][3], o9, wf23.y);
        }
    }

#pragma unroll
    for (int c = 0; c < CO_PT; c++) {
        float* orow = out + (((b << 3) + cobase + c) << LSHIFT) + l;
        ulonglong2 s0, s1;
        s0.x = acc[c][0]; s0.y = acc[c][1];
        s1.x = acc[c][2]; s1.y = acc[c][3];
        *reinterpret_cast<ulonglong2*>(orow)     = s0;
        *reinterpret_cast<ulonglong2*>(orow + 4) = s1;
    }
}

extern "C" void kernel_launch(void* const* d_in, const int* in_sizes, int n_in,
                              void* d_out, int out_size) {
    const float* x    = (const float*)d_in[0];
    const float* W    = (const float*)d_in[1];
    const float* bias = (const float*)d_in[2];
    float* out        = (float*)d_out;

    // 128 tiles per block (x2 co-halves = 256 threads); total tiles = 64*8192
    const int threads = 256;
    const int blocks  = (BATCH * TPR) / 128;   // 524288 / 128 = 4096
    convPbc_1d_kernel<<<blocks, threads>>>(x, W, bias, out);
}